// round 15
// baseline (speedup 1.0000x reference)
#include <cuda_runtime.h>
#include <cuda_bf16.h>
#include <math.h>

#define BATCH 32
#define FREQ  34
#define TLEN  1000
#define FD    10
#define CCH   64
#define HID   640
#define H3    1920
#define MSKS  200
#define BN_EPS 1e-5f
#define NBG   128      // persistent GRU blocks
#define HB    (HID * BATCH)   // 20480

// ---------------- device scratch (no runtime allocation allowed) -----------
__device__ float d_hp[2 * BATCH * FREQ * TLEN];      // [sign][b][f][t]
__device__ float d_dk[HID * 14 * 9];                 // DCLS kernels
__device__ float d_y[BATCH * HID * TLEN];            // conv out (b, fd*64+c, t)
__device__ float d_scale[CCH], d_shift[CCH];
__device__ float d_seq[TLEN * BATCH * HID];          // GEMM A (t*32+b, h)
__device__ float d_xp[TLEN * H3 * BATCH];            // x_proj TRANSPOSED (t, col, b)
__device__ float d_hs[(TLEN + 1) * HB];              // hidden ring [t][m][b]
__device__ unsigned d_cnt;

__device__ __forceinline__ float sigf(float x) { return 1.0f / (1.0f + __expf(-x)); }

// ---- packed f32x2 helpers (sm_100+: fma.rn.f32x2 -> FFMA2, bit-exact fp32) --
typedef unsigned long long ull_t;
__device__ __forceinline__ ull_t pack2(float lo, float hi) {
    ull_t r; asm("mov.b64 %0, {%1, %2};" : "=l"(r) : "f"(lo), "f"(hi)); return r;
}
__device__ __forceinline__ void unpack2(ull_t v, float& lo, float& hi) {
    asm("mov.b64 {%0, %1}, %2;" : "=f"(lo), "=f"(hi) : "l"(v));
}
__device__ __forceinline__ ull_t fma2(ull_t a, ull_t b, ull_t c) {
    ull_t d; asm("fma.rn.f32x2 %0, %1, %2, %3;" : "=l"(d) : "l"(a), "l"(b), "l"(c));
    return d;
}

// ---------------- init: h0 = 0, barrier counter = 0 ------------------------
__global__ void k_init() {
    int i = blockIdx.x * 256 + threadIdx.x;
    if (i < HB) d_hs[i] = 0.0f;
    if (i == 0) d_cnt = 0u;
}

// ---------------- K1: EMA high-pass + rectification ------------------------
__global__ void k_front(const float* __restrict__ x,
                        const float* __restrict__ a_vals,
                        const float* __restrict__ w_vals) {
    int f = blockIdx.x, b = blockIdx.y;
    __shared__ float xs[TLEN];
    __shared__ float ws[MSKS];
    const float* xr = x + (b * FREQ + f) * TLEN;
    for (int i = threadIdx.x; i < TLEN; i += blockDim.x) xs[i] = xr[i];
    float a = a_vals[f];
    for (int j = threadIdx.x; j < MSKS; j += blockDim.x)
        ws[j] = a * powf(1.0f - a, (float)j);
    __syncthreads();
    float wv = w_vals[f];
    for (int t = threadIdx.x; t < TLEN; t += blockDim.x) {
        float low0 = 0.0f, low1 = 0.0f;      // 2 chains to halve dependent-FMA latency
        int jmax = min(MSKS - 1, t);
        int j = 0;
        for (; j + 1 <= jmax; j += 2) {
            low0 = fmaf(ws[j], xs[t - j], low0);
            low1 = fmaf(ws[j + 1], xs[t - j - 1], low1);
        }
        if (j <= jmax) low0 = fmaf(ws[j], xs[t - j], low0);
        float hp = xs[t] - wv * (low0 + low1);
        int base = (b * FREQ + f) * TLEN + t;
        d_hp[base] = fmaxf(hp, 0.0f);
        d_hp[BATCH * FREQ * TLEN + base] = fmaxf(-hp, 0.0f);
    }
}

// ---------------- build DCLS triangular kernels ----------------------------
__global__ void k_dk(const float* __restrict__ w, const float* __restrict__ p) {
    int idx = blockIdx.x * 256 + threadIdx.x;   // over 640*14
    if (idx < HID * 14) {
        float wp = w[idx];
        float pp = fminf(fmaxf(p[idx], 0.0f), 8.0f);
        #pragma unroll
        for (int tau = 0; tau < 9; tau++)
            d_dk[idx * 9 + tau] = wp * fmaxf(1.0f - fabsf((float)tau - pp), 0.0f);
    }
}

// ---------------- K2: grouped DCLS conv. grid (5, 10, 32) ------------------
__global__ void k_dcls(const float* __restrict__ dcls_b) {
    int tc = blockIdx.x, fd = blockIdx.y, b = blockIdx.z;
    int t0 = tc * 200;
    __shared__ float us[14][208];
    __shared__ float dks[CCH * 126];
    for (int idx = threadIdx.x; idx < 14 * 208; idx += 256) {
        int i = idx / 208, tt = idx % 208;
        int tg = t0 - 4 + tt;
        float v = 0.0f;
        if (tg >= 0 && tg < TLEN) {
            int f = fd * 3 + (i % 7);
            v = d_hp[(((i / 7) * BATCH + b) * FREQ + f) * TLEN + tg];
        }
        us[i][tt] = v;
    }
    for (int idx = threadIdx.x; idx < CCH * 126; idx += 256)
        dks[idx] = d_dk[fd * CCH * 126 + idx];
    __syncthreads();

    int c = threadIdx.x & 63;
    int tq = threadIdx.x >> 6;                 // 0..3 (50 t each)
    float bias = dcls_b[fd * CCH + c];
    float* ybase = d_y + ((b * HID + fd * CCH + c) * TLEN) + t0;

    for (int g = 0; g < 5; g++) {
        int tl = tq * 50 + g * 10;
        float acc[10];
        #pragma unroll
        for (int j = 0; j < 10; j++) acc[j] = 0.0f;
        for (int i = 0; i < 14; i++) {
            float w[9];
            #pragma unroll
            for (int tau = 0; tau < 9; tau++) w[tau] = dks[c * 126 + i * 9 + tau];
            float u[18];
            #pragma unroll
            for (int q = 0; q < 18; q++) u[q] = us[i][tl + q];
            #pragma unroll
            for (int j = 0; j < 10; j++)
                #pragma unroll
                for (int tau = 0; tau < 9; tau++)
                    acc[j] = fmaf(w[tau], u[j + tau], acc[j]);
        }
        #pragma unroll
        for (int j = 0; j < 10; j++) ybase[tl + j] = acc[j] + bias;
    }
}

// ---------------- K3: per-channel BN stats ---------------------------------
__global__ void k_stats(const float* __restrict__ gamma, const float* __restrict__ beta) {
    int c = blockIdx.x;
    float s = 0.0f, s2 = 0.0f;
    for (int r = 0; r < BATCH * FD; r++) {
        const float* p = d_y + (r * CCH + c) * TLEN;
        for (int t = threadIdx.x; t < TLEN; t += 256) {
            float v = p[t];
            s += v; s2 = fmaf(v, v, s2);
        }
    }
    __shared__ float rs[256], rs2[256];
    rs[threadIdx.x] = s; rs2[threadIdx.x] = s2;
    __syncthreads();
    for (int off = 128; off > 0; off >>= 1) {
        if (threadIdx.x < off) {
            rs[threadIdx.x]  += rs[threadIdx.x + off];
            rs2[threadIdx.x] += rs2[threadIdx.x + off];
        }
        __syncthreads();
    }
    if (threadIdx.x == 0) {
        const float n = (float)(BATCH * FD * TLEN);
        float mean = rs[0] / n;
        float var = rs2[0] / n - mean * mean;
        float sc = rsqrtf(var + BN_EPS) * gamma[c];
        d_scale[c] = sc;
        d_shift[c] = beta[c] - mean * sc;
    }
}

// ---------------- K4: BN + sigmoid + relayout ------------------------------
// seq[t, b, h] with h = c*10 + fd, from d_y[b, fd*64+c, t]
__global__ void k_relayout() {
    __shared__ float ys[HID][17];
    __shared__ float sc[CCH], sh[CCH];
    int b = blockIdx.y;
    int t0 = blockIdx.x * 16;
    if (threadIdx.x < CCH) { sc[threadIdx.x] = d_scale[threadIdx.x]; sh[threadIdx.x] = d_shift[threadIdx.x]; }
    int tcnt = min(16, TLEN - t0);
    for (int idx = threadIdx.x; idx < HID * 16; idx += 256) {
        int ch = idx >> 4, tt = idx & 15;
        ys[ch][tt] = (tt < tcnt) ? d_y[(b * HID + ch) * TLEN + t0 + tt] : 0.0f;
    }
    __syncthreads();
    for (int tt = 0; tt < tcnt; tt++) {
        for (int h = threadIdx.x; h < HID; h += 256) {
            int c = h / 10, fd = h % 10;
            float z = ys[fd * CCH + c][tt] * sc[c] + sh[c];
            d_seq[((t0 + tt) * BATCH + b) * HID + h] = sigf(z);
        }
    }
}

// ---------------- K5: x_proj GEMM (32000x640)*(1920x640)^T + b_ih ----------
// 128x64x16 tiles, double-buffered smem, packed FFMA2 inner product.
// Output TRANSPOSED: d_xp[(t*1920+col)*32+b]
__global__ __launch_bounds__(256, 2) void k_gemm(const float* __restrict__ Wih,
                                                 const float* __restrict__ bih) {
    __shared__ __align__(16) float As[2][16][128];
    __shared__ __align__(16) float Bs[2][16][64];
    int tid = threadIdx.x;
    const float* Ag = d_seq + (size_t)blockIdx.y * 128 * HID;
    const float* Bg = Wih  + (size_t)blockIdx.x * 64 * HID;

    int ar = tid & 127, ak = (tid >> 7) * 8;   // A loader: row, k-offset (8 k)
    int bn_ = tid & 63, bk_ = (tid >> 6) * 4;  // B loader: n,   k-offset (4 k)

    int ty = tid >> 4, tx = tid & 15;          // compute: 8 rows (4 pairs) x 4 cols
    ull_t acc2[4][4];
    #pragma unroll
    for (int i = 0; i < 4; i++)
        #pragma unroll
        for (int j = 0; j < 4; j++) acc2[i][j] = pack2(0.0f, 0.0f);

    float4 pa0 = *(const float4*)(Ag + ar * HID + ak);
    float4 pa1 = *(const float4*)(Ag + ar * HID + ak + 4);
    float4 pb  = *(const float4*)(Bg + bn_ * HID + bk_);

    // prologue: fill buffer 0
    As[0][ak + 0][ar] = pa0.x; As[0][ak + 1][ar] = pa0.y;
    As[0][ak + 2][ar] = pa0.z; As[0][ak + 3][ar] = pa0.w;
    As[0][ak + 4][ar] = pa1.x; As[0][ak + 5][ar] = pa1.y;
    As[0][ak + 6][ar] = pa1.z; As[0][ak + 7][ar] = pa1.w;
    Bs[0][bk_ + 0][bn_] = pb.x; Bs[0][bk_ + 1][bn_] = pb.y;
    Bs[0][bk_ + 2][bn_] = pb.z; Bs[0][bk_ + 3][bn_] = pb.w;
    __syncthreads();

    for (int kt = 0; kt < 40; kt++) {
        int cur = kt & 1, nxt = cur ^ 1;
        if (kt < 39) {
            int k0 = (kt + 1) * 16;
            pa0 = *(const float4*)(Ag + ar * HID + k0 + ak);
            pa1 = *(const float4*)(Ag + ar * HID + k0 + ak + 4);
            pb  = *(const float4*)(Bg + bn_ * HID + k0 + bk_);
        }
        #pragma unroll
        for (int k = 0; k < 16; k++) {
            // A: rows ty*8..+7 = 4 adjacent packed pairs (little-endian: lo = even row)
            ulonglong2 A01 = *(const ulonglong2*)&As[cur][k][ty * 8];
            ulonglong2 A23 = *(const ulonglong2*)&As[cur][k][ty * 8 + 4];
            float4 b4 = *(const float4*)&Bs[cur][k][tx * 4];
            ull_t bb0 = pack2(b4.x, b4.x);
            ull_t bb1 = pack2(b4.y, b4.y);
            ull_t bb2 = pack2(b4.z, b4.z);
            ull_t bb3 = pack2(b4.w, b4.w);
            acc2[0][0] = fma2(A01.x, bb0, acc2[0][0]);
            acc2[1][0] = fma2(A01.y, bb0, acc2[1][0]);
            acc2[2][0] = fma2(A23.x, bb0, acc2[2][0]);
            acc2[3][0] = fma2(A23.y, bb0, acc2[3][0]);
            acc2[0][1] = fma2(A01.x, bb1, acc2[0][1]);
            acc2[1][1] = fma2(A01.y, bb1, acc2[1][1]);
            acc2[2][1] = fma2(A23.x, bb1, acc2[2][1]);
            acc2[3][1] = fma2(A23.y, bb1, acc2[3][1]);
            acc2[0][2] = fma2(A01.x, bb2, acc2[0][2]);
            acc2[1][2] = fma2(A01.y, bb2, acc2[1][2]);
            acc2[2][2] = fma2(A23.x, bb2, acc2[2][2]);
            acc2[3][2] = fma2(A23.y, bb2, acc2[3][2]);
            acc2[0][3] = fma2(A01.x, bb3, acc2[0][3]);
            acc2[1][3] = fma2(A01.y, bb3, acc2[1][3]);
            acc2[2][3] = fma2(A23.x, bb3, acc2[2][3]);
            acc2[3][3] = fma2(A23.y, bb3, acc2[3][3]);
        }
        if (kt < 39) {
            As[nxt][ak + 0][ar] = pa0.x; As[nxt][ak + 1][ar] = pa0.y;
            As[nxt][ak + 2][ar] = pa0.z; As[nxt][ak + 3][ar] = pa0.w;
            As[nxt][ak + 4][ar] = pa1.x; As[nxt][ak + 5][ar] = pa1.y;
            As[nxt][ak + 6][ar] = pa1.z; As[nxt][ak + 7][ar] = pa1.w;
            Bs[nxt][bk_ + 0][bn_] = pb.x; Bs[nxt][bk_ + 1][bn_] = pb.y;
            Bs[nxt][bk_ + 2][bn_] = pb.z; Bs[nxt][bk_ + 3][bn_] = pb.w;
            __syncthreads();
        }
    }
    // unpack accumulators: acc[i][j], i = row within 8-row group
    float acc[8][4];
    #pragma unroll
    for (int p = 0; p < 4; p++)
        #pragma unroll
        for (int j = 0; j < 4; j++)
            unpack2(acc2[p][j], acc[2 * p][j], acc[2 * p + 1][j]);

    // epilogue: rows ty*8..ty*8+7 are 8 consecutive b within one t
    int col = blockIdx.x * 64 + tx * 4;
    float4 bb = *(const float4*)(bih + col);
    float bias4[4] = {bb.x, bb.y, bb.z, bb.w};
    int t  = blockIdx.y * 4 + (ty >> 2);
    int b0 = (ty & 3) * 8;
    #pragma unroll
    for (int j = 0; j < 4; j++) {
        size_t base = ((size_t)t * H3 + col + j) * BATCH + b0;
        float4 lo = make_float4(acc[0][j] + bias4[j], acc[1][j] + bias4[j],
                                acc[2][j] + bias4[j], acc[3][j] + bias4[j]);
        float4 hi = make_float4(acc[4][j] + bias4[j], acc[5][j] + bias4[j],
                                acc[6][j] + bias4[j], acc[7][j] + bias4[j]);
        *(float4*)&d_xp[base]     = lo;
        *(float4*)&d_xp[base + 4] = hi;
    }
}

// ---------------- K6: persistent GRU scan (k-split, FFMA2) ------------------
// 128 blocks x 128 threads; block bk owns hidden units m0=bk*5..+4.
// W_hh repacked in smem as Wsm2[k][16]: rows l=gate*5+j (15 real + 1 zero pad),
// row-pairs adjacent so LDS.128 yields 2 packed pairs. Warp w covers k-quarter
// [w*160,(w+1)*160) for ALL 15 rows; lane = batch b; h read coalesced from
// global; one {h,h} pack + 8 FFMA2 per k. Partials reduced through smem.
__global__ __launch_bounds__(128, 1) void k_gru(const float* __restrict__ Whh,
                                                const float* __restrict__ bhh) {
    __shared__ __align__(16) float Wsm2[HID][16];   // 40960 B
    __shared__ float part[4][15][32];               //  7680 B
    __shared__ float bhs[15];

    int bk = blockIdx.x, tid = threadIdx.x;
    int m0 = bk * 5;

    for (int idx = tid; idx < 16 * HID; idx += 128) {
        int k = idx >> 4, l = idx & 15;
        Wsm2[k][l] = (l < 15) ? Whh[((l / 5) * HID + m0 + (l % 5)) * HID + k] : 0.0f;
    }
    if (tid < 15) bhs[tid] = bhh[(tid / 5) * HID + m0 + tid % 5];
    __syncthreads();

    int b = tid & 31, w = tid >> 5;
    int k0w = w * 160;

    // gate-item assignment: item A = idx tid (j=tid>>5), item B = idx tid+128 (j=4, tid<32)
    int jA = tid >> 5, bbA = tid & 31;
    int mA = m0 + jA;
    bool hasB = (tid < 32);
    int mB = m0 + 4, bbB = tid;

    unsigned tgt = 0u;
    for (int t = 0; t < TLEN; t++) {
        const float* hb = d_hs + (size_t)t * HB + b;
        ull_t acc2[8];
        #pragma unroll
        for (int p = 0; p < 8; p++) acc2[p] = pack2(0.0f, 0.0f);

        #pragma unroll 4
        for (int kk = 0; kk < 160; kk += 2) {
            int k = k0w + kk;
            float h0 = hb[(k + 0) * 32];
            float h1 = hb[(k + 1) * 32];
            ull_t hh0 = pack2(h0, h0);
            ull_t hh1 = pack2(h1, h1);
            const ulonglong2* wp0 = (const ulonglong2*)&Wsm2[k][0];
            ulonglong2 q0 = wp0[0], q1 = wp0[1], q2 = wp0[2], q3 = wp0[3];
            acc2[0] = fma2(q0.x, hh0, acc2[0]);
            acc2[1] = fma2(q0.y, hh0, acc2[1]);
            acc2[2] = fma2(q1.x, hh0, acc2[2]);
            acc2[3] = fma2(q1.y, hh0, acc2[3]);
            acc2[4] = fma2(q2.x, hh0, acc2[4]);
            acc2[5] = fma2(q2.y, hh0, acc2[5]);
            acc2[6] = fma2(q3.x, hh0, acc2[6]);
            acc2[7] = fma2(q3.y, hh0, acc2[7]);
            const ulonglong2* wp1 = (const ulonglong2*)&Wsm2[k + 1][0];
            ulonglong2 r0 = wp1[0], r1 = wp1[1], r2 = wp1[2], r3 = wp1[3];
            acc2[0] = fma2(r0.x, hh1, acc2[0]);
            acc2[1] = fma2(r0.y, hh1, acc2[1]);
            acc2[2] = fma2(r1.x, hh1, acc2[2]);
            acc2[3] = fma2(r1.y, hh1, acc2[3]);
            acc2[4] = fma2(r2.x, hh1, acc2[4]);
            acc2[5] = fma2(r2.y, hh1, acc2[5]);
            acc2[6] = fma2(r3.x, hh1, acc2[6]);
            acc2[7] = fma2(r3.y, hh1, acc2[7]);
        }
        // unpack 8 pairs -> rows 0..14 (pair 7 hi = pad, discarded)
        {
            float lo, hi;
            #pragma unroll
            for (int p = 0; p < 7; p++) {
                unpack2(acc2[p], lo, hi);
                part[w][2 * p][b] = lo;
                part[w][2 * p + 1][b] = hi;
            }
            unpack2(acc2[7], lo, hi);
            part[w][14][b] = lo;
        }

        // prefetch gate inputs (independent of part[]) to hide L2 latency
        const float* xpt = d_xp + (size_t)t * H3 * BATCH;
        const float* hsl = d_hs + (size_t)t * HB;
        float xrA = xpt[(size_t)mA * BATCH + bbA];
        float xzA = xpt[(size_t)(640 + mA) * BATCH + bbA];
        float xnA = xpt[(size_t)(1280 + mA) * BATCH + bbA];
        float hoA = hsl[mA * 32 + bbA];
        float xrB = 0.f, xzB = 0.f, xnB = 0.f, hoB = 0.f;
        if (hasB) {
            xrB = xpt[(size_t)mB * BATCH + bbB];
            xzB = xpt[(size_t)(640 + mB) * BATCH + bbB];
            xnB = xpt[(size_t)(1280 + mB) * BATCH + bbB];
            hoB = hsl[mB * 32 + bbB];
        }
        __syncthreads();

        float* hnew = d_hs + (size_t)(t + 1) * HB;
        {
            float gr = part[0][jA][bbA] + part[1][jA][bbA] + part[2][jA][bbA] + part[3][jA][bbA];
            float gz = part[0][5 + jA][bbA] + part[1][5 + jA][bbA] + part[2][5 + jA][bbA] + part[3][5 + jA][bbA];
            float gn = part[0][10 + jA][bbA] + part[1][10 + jA][bbA] + part[2][10 + jA][bbA] + part[3][10 + jA][bbA];
            float r = sigf(xrA + gr + bhs[jA]);
            float z = sigf(xzA + gz + bhs[5 + jA]);
            float n = tanhf(xnA + r * (gn + bhs[10 + jA]));
            hnew[mA * 32 + bbA] = (1.0f - z) * n + z * hoA;
        }
        if (hasB) {
            float gr = part[0][4][bbB] + part[1][4][bbB] + part[2][4][bbB] + part[3][4][bbB];
            float gz = part[0][9][bbB] + part[1][9][bbB] + part[2][9][bbB] + part[3][9][bbB];
            float gn = part[0][14][bbB] + part[1][14][bbB] + part[2][14][bbB] + part[3][14][bbB];
            float r = sigf(xrB + gr + bhs[4]);
            float z = sigf(xzB + gz + bhs[9]);
            float n = tanhf(xnB + r * (gn + bhs[14]));
            hnew[mB * 32 + bbB] = (1.0f - z) * n + z * hoB;
        }
        __syncthreads();

        // grid barrier (monotonic counter; ring buffer => every read is first-touch)
        if (tid == 0) {
            __threadfence();
            atomicAdd(&d_cnt, 1u);
            tgt += (unsigned)NBG;
            while (*(volatile unsigned*)&d_cnt < tgt) { __nanosleep(64); }
            __threadfence();
        }
        __syncthreads();
    }
}

// ---------------- K7: FC head ----------------------------------------------
__global__ void k_fc(const float* __restrict__ fcw, const float* __restrict__ fcb,
                     float* __restrict__ out) {
    int t = blockIdx.x;
    int b = threadIdx.x & 31, mg = threadIdx.x >> 5;
    const float* h = d_hs + (size_t)(t + 1) * HB;
    float acc = 0.0f;
    for (int m = mg * 160; m < mg * 160 + 160; m++)
        acc = fmaf(fcw[m], h[m * 32 + b], acc);
    __shared__ float red[4][32];
    red[mg][b] = acc;
    __syncthreads();
    if (mg == 0)
        out[b * TLEN + t] = red[0][b] + red[1][b] + red[2][b] + red[3][b] + fcb[0];
}

// ---------------- launch ----------------------------------------------------
extern "C" void kernel_launch(void* const* d_in, const int* in_sizes, int n_in,
                              void* d_out, int out_size) {
    const float* x      = (const float*)d_in[0];
    const float* a_vals = (const float*)d_in[1];
    const float* w_vals = (const float*)d_in[2];
    const float* dcls_w = (const float*)d_in[3];
    const float* dcls_p = (const float*)d_in[4];
    const float* dcls_b = (const float*)d_in[5];
    const float* gamma  = (const float*)d_in[6];
    const float* beta   = (const float*)d_in[7];
    const float* W_ih   = (const float*)d_in[8];
    const float* W_hh   = (const float*)d_in[9];
    const float* b_ih   = (const float*)d_in[10];
    const float* b_hh   = (const float*)d_in[11];
    const float* fc_w   = (const float*)d_in[12];
    const float* fc_b   = (const float*)d_in[13];
    float* out = (float*)d_out;

    k_init<<<(HB + 255) / 256, 256>>>();
    k_front<<<dim3(FREQ, BATCH), 256>>>(x, a_vals, w_vals);
    k_dk<<<35, 256>>>(dcls_w, dcls_p);
    k_dcls<<<dim3(5, FD, BATCH), 256>>>(dcls_b);
    k_stats<<<CCH, 256>>>(gamma, beta);
    k_relayout<<<dim3(63, BATCH), 256>>>();
    k_gemm<<<dim3(30, 250), 256>>>(W_ih, b_ih);
    k_gru<<<NBG, 128>>>(W_hh, b_hh);
    k_fc<<<TLEN, 128>>>(fc_w, fc_b, out);
}

// round 17
// speedup vs baseline: 1.2171x; 1.2171x over previous
#include <cuda_runtime.h>
#include <cuda_bf16.h>
#include <math.h>

#define BATCH 32
#define FREQ  34
#define TLEN  1000
#define FD    10
#define CCH   64
#define HID   640
#define H3    1920
#define MSKS  200
#define BN_EPS 1e-5f
#define NBG   128      // persistent GRU blocks
#define HB    (HID * BATCH)   // 20480

// ---------------- device scratch (no runtime allocation allowed) -----------
__device__ float d_hp[2 * BATCH * FREQ * TLEN];      // [sign][b][f][t]
__device__ float d_dk[HID * 14 * 9];                 // DCLS kernels
__device__ float d_y[BATCH * HID * TLEN];            // conv out (b, fd*64+c, t)
__device__ float d_scale[CCH], d_shift[CCH];
__device__ float d_seq[TLEN * BATCH * HID];          // GEMM A (t*32+b, h)
__device__ float d_xp[TLEN * H3 * BATCH];            // x_proj TRANSPOSED (t, col, b)
__device__ float d_hs[(TLEN + 1) * HB];              // hidden ring [t][m][b]
__device__ unsigned d_cnt;

__device__ __forceinline__ float sigf(float x) { return 1.0f / (1.0f + __expf(-x)); }

// ---- packed f32x2 helpers (sm_100+: fma.rn.f32x2 -> FFMA2, bit-exact fp32) --
typedef unsigned long long ull_t;
__device__ __forceinline__ ull_t pack2(float lo, float hi) {
    ull_t r; asm("mov.b64 %0, {%1, %2};" : "=l"(r) : "f"(lo), "f"(hi)); return r;
}
__device__ __forceinline__ void unpack2(ull_t v, float& lo, float& hi) {
    asm("mov.b64 {%0, %1}, %2;" : "=f"(lo), "=f"(hi) : "l"(v));
}
__device__ __forceinline__ ull_t fma2(ull_t a, ull_t b, ull_t c) {
    ull_t d; asm("fma.rn.f32x2 %0, %1, %2, %3;" : "=l"(d) : "l"(a), "l"(b), "l"(c));
    return d;
}

// ---------------- init: h0 = 0, barrier counter = 0 ------------------------
__global__ void k_init() {
    int i = blockIdx.x * 256 + threadIdx.x;
    if (i < HB) d_hs[i] = 0.0f;
    if (i == 0) d_cnt = 0u;
}

// ---------------- K1: EMA high-pass + rectification ------------------------
__global__ void k_front(const float* __restrict__ x,
                        const float* __restrict__ a_vals,
                        const float* __restrict__ w_vals) {
    int f = blockIdx.x, b = blockIdx.y;
    __shared__ float xs[TLEN];
    __shared__ float ws[MSKS];
    const float* xr = x + (b * FREQ + f) * TLEN;
    for (int i = threadIdx.x; i < TLEN; i += blockDim.x) xs[i] = xr[i];
    float a = a_vals[f];
    for (int j = threadIdx.x; j < MSKS; j += blockDim.x)
        ws[j] = a * powf(1.0f - a, (float)j);
    __syncthreads();
    float wv = w_vals[f];
    for (int t = threadIdx.x; t < TLEN; t += blockDim.x) {
        float low0 = 0.0f, low1 = 0.0f;
        int jmax = min(MSKS - 1, t);
        int j = 0;
        for (; j + 1 <= jmax; j += 2) {
            low0 = fmaf(ws[j], xs[t - j], low0);
            low1 = fmaf(ws[j + 1], xs[t - j - 1], low1);
        }
        if (j <= jmax) low0 = fmaf(ws[j], xs[t - j], low0);
        float hp = xs[t] - wv * (low0 + low1);
        int base = (b * FREQ + f) * TLEN + t;
        d_hp[base] = fmaxf(hp, 0.0f);
        d_hp[BATCH * FREQ * TLEN + base] = fmaxf(-hp, 0.0f);
    }
}

// ---------------- build DCLS triangular kernels ----------------------------
__global__ void k_dk(const float* __restrict__ w, const float* __restrict__ p) {
    int idx = blockIdx.x * 256 + threadIdx.x;   // over 640*14
    if (idx < HID * 14) {
        float wp = w[idx];
        float pp = fminf(fmaxf(p[idx], 0.0f), 8.0f);
        #pragma unroll
        for (int tau = 0; tau < 9; tau++)
            d_dk[idx * 9 + tau] = wp * fmaxf(1.0f - fabsf((float)tau - pp), 0.0f);
    }
}

// ---------------- K2: grouped DCLS conv. grid (5, 10, 32) ------------------
__global__ void k_dcls(const float* __restrict__ dcls_b) {
    int tc = blockIdx.x, fd = blockIdx.y, b = blockIdx.z;
    int t0 = tc * 200;
    __shared__ float us[14][208];
    __shared__ float dks[CCH * 126];
    for (int idx = threadIdx.x; idx < 14 * 208; idx += 256) {
        int i = idx / 208, tt = idx % 208;
        int tg = t0 - 4 + tt;
        float v = 0.0f;
        if (tg >= 0 && tg < TLEN) {
            int f = fd * 3 + (i % 7);
            v = d_hp[(((i / 7) * BATCH + b) * FREQ + f) * TLEN + tg];
        }
        us[i][tt] = v;
    }
    for (int idx = threadIdx.x; idx < CCH * 126; idx += 256)
        dks[idx] = d_dk[fd * CCH * 126 + idx];
    __syncthreads();

    int c = threadIdx.x & 63;
    int tq = threadIdx.x >> 6;
    float bias = dcls_b[fd * CCH + c];
    float* ybase = d_y + ((b * HID + fd * CCH + c) * TLEN) + t0;

    for (int g = 0; g < 5; g++) {
        int tl = tq * 50 + g * 10;
        float acc[10];
        #pragma unroll
        for (int j = 0; j < 10; j++) acc[j] = 0.0f;
        for (int i = 0; i < 14; i++) {
            float w[9];
            #pragma unroll
            for (int tau = 0; tau < 9; tau++) w[tau] = dks[c * 126 + i * 9 + tau];
            float u[18];
            #pragma unroll
            for (int q = 0; q < 18; q++) u[q] = us[i][tl + q];
            #pragma unroll
            for (int j = 0; j < 10; j++)
                #pragma unroll
                for (int tau = 0; tau < 9; tau++)
                    acc[j] = fmaf(w[tau], u[j + tau], acc[j]);
        }
        #pragma unroll
        for (int j = 0; j < 10; j++) ybase[tl + j] = acc[j] + bias;
    }
}

// ---------------- K3: per-channel BN stats ---------------------------------
__global__ void k_stats(const float* __restrict__ gamma, const float* __restrict__ beta) {
    int c = blockIdx.x;
    float s = 0.0f, s2 = 0.0f;
    for (int r = 0; r < BATCH * FD; r++) {
        const float* p = d_y + (r * CCH + c) * TLEN;
        for (int t = threadIdx.x; t < TLEN; t += 256) {
            float v = p[t];
            s += v; s2 = fmaf(v, v, s2);
        }
    }
    __shared__ float rs[256], rs2[256];
    rs[threadIdx.x] = s; rs2[threadIdx.x] = s2;
    __syncthreads();
    for (int off = 128; off > 0; off >>= 1) {
        if (threadIdx.x < off) {
            rs[threadIdx.x]  += rs[threadIdx.x + off];
            rs2[threadIdx.x] += rs2[threadIdx.x + off];
        }
        __syncthreads();
    }
    if (threadIdx.x == 0) {
        const float n = (float)(BATCH * FD * TLEN);
        float mean = rs[0] / n;
        float var = rs2[0] / n - mean * mean;
        float sc = rsqrtf(var + BN_EPS) * gamma[c];
        d_scale[c] = sc;
        d_shift[c] = beta[c] - mean * sc;
    }
}

// ---------------- K4: BN + sigmoid + relayout ------------------------------
__global__ void k_relayout() {
    __shared__ float ys[HID][17];
    __shared__ float sc[CCH], sh[CCH];
    int b = blockIdx.y;
    int t0 = blockIdx.x * 16;
    if (threadIdx.x < CCH) { sc[threadIdx.x] = d_scale[threadIdx.x]; sh[threadIdx.x] = d_shift[threadIdx.x]; }
    int tcnt = min(16, TLEN - t0);
    for (int idx = threadIdx.x; idx < HID * 16; idx += 256) {
        int ch = idx >> 4, tt = idx & 15;
        ys[ch][tt] = (tt < tcnt) ? d_y[(b * HID + ch) * TLEN + t0 + tt] : 0.0f;
    }
    __syncthreads();
    for (int tt = 0; tt < tcnt; tt++) {
        for (int h = threadIdx.x; h < HID; h += 256) {
            int c = h / 10, fd = h % 10;
            float z = ys[fd * CCH + c][tt] * sc[c] + sh[c];
            d_seq[((t0 + tt) * BATCH + b) * HID + h] = sigf(z);
        }
    }
}

// ---------------- K5: x_proj GEMM (32000x640)*(1920x640)^T + b_ih ----------
__global__ __launch_bounds__(256, 2) void k_gemm(const float* __restrict__ Wih,
                                                 const float* __restrict__ bih) {
    __shared__ __align__(16) float As[2][16][128];
    __shared__ __align__(16) float Bs[2][16][64];
    int tid = threadIdx.x;
    const float* Ag = d_seq + (size_t)blockIdx.y * 128 * HID;
    const float* Bg = Wih  + (size_t)blockIdx.x * 64 * HID;

    int ar = tid & 127, ak = (tid >> 7) * 8;
    int bn_ = tid & 63, bk_ = (tid >> 6) * 4;

    int ty = tid >> 4, tx = tid & 15;
    ull_t acc2[4][4];
    #pragma unroll
    for (int i = 0; i < 4; i++)
        #pragma unroll
        for (int j = 0; j < 4; j++) acc2[i][j] = pack2(0.0f, 0.0f);

    float4 pa0 = *(const float4*)(Ag + ar * HID + ak);
    float4 pa1 = *(const float4*)(Ag + ar * HID + ak + 4);
    float4 pb  = *(const float4*)(Bg + bn_ * HID + bk_);

    As[0][ak + 0][ar] = pa0.x; As[0][ak + 1][ar] = pa0.y;
    As[0][ak + 2][ar] = pa0.z; As[0][ak + 3][ar] = pa0.w;
    As[0][ak + 4][ar] = pa1.x; As[0][ak + 5][ar] = pa1.y;
    As[0][ak + 6][ar] = pa1.z; As[0][ak + 7][ar] = pa1.w;
    Bs[0][bk_ + 0][bn_] = pb.x; Bs[0][bk_ + 1][bn_] = pb.y;
    Bs[0][bk_ + 2][bn_] = pb.z; Bs[0][bk_ + 3][bn_] = pb.w;
    __syncthreads();

    for (int kt = 0; kt < 40; kt++) {
        int cur = kt & 1, nxt = cur ^ 1;
        if (kt < 39) {
            int k0 = (kt + 1) * 16;
            pa0 = *(const float4*)(Ag + ar * HID + k0 + ak);
            pa1 = *(const float4*)(Ag + ar * HID + k0 + ak + 4);
            pb  = *(const float4*)(Bg + bn_ * HID + k0 + bk_);
        }
        #pragma unroll
        for (int k = 0; k < 16; k++) {
            ulonglong2 A01 = *(const ulonglong2*)&As[cur][k][ty * 8];
            ulonglong2 A23 = *(const ulonglong2*)&As[cur][k][ty * 8 + 4];
            float4 b4 = *(const float4*)&Bs[cur][k][tx * 4];
            ull_t bb0 = pack2(b4.x, b4.x);
            ull_t bb1 = pack2(b4.y, b4.y);
            ull_t bb2 = pack2(b4.z, b4.z);
            ull_t bb3 = pack2(b4.w, b4.w);
            acc2[0][0] = fma2(A01.x, bb0, acc2[0][0]);
            acc2[1][0] = fma2(A01.y, bb0, acc2[1][0]);
            acc2[2][0] = fma2(A23.x, bb0, acc2[2][0]);
            acc2[3][0] = fma2(A23.y, bb0, acc2[3][0]);
            acc2[0][1] = fma2(A01.x, bb1, acc2[0][1]);
            acc2[1][1] = fma2(A01.y, bb1, acc2[1][1]);
            acc2[2][1] = fma2(A23.x, bb1, acc2[2][1]);
            acc2[3][1] = fma2(A23.y, bb1, acc2[3][1]);
            acc2[0][2] = fma2(A01.x, bb2, acc2[0][2]);
            acc2[1][2] = fma2(A01.y, bb2, acc2[1][2]);
            acc2[2][2] = fma2(A23.x, bb2, acc2[2][2]);
            acc2[3][2] = fma2(A23.y, bb2, acc2[3][2]);
            acc2[0][3] = fma2(A01.x, bb3, acc2[0][3]);
            acc2[1][3] = fma2(A01.y, bb3, acc2[1][3]);
            acc2[2][3] = fma2(A23.x, bb3, acc2[2][3]);
            acc2[3][3] = fma2(A23.y, bb3, acc2[3][3]);
        }
        if (kt < 39) {
            As[nxt][ak + 0][ar] = pa0.x; As[nxt][ak + 1][ar] = pa0.y;
            As[nxt][ak + 2][ar] = pa0.z; As[nxt][ak + 3][ar] = pa0.w;
            As[nxt][ak + 4][ar] = pa1.x; As[nxt][ak + 5][ar] = pa1.y;
            As[nxt][ak + 6][ar] = pa1.z; As[nxt][ak + 7][ar] = pa1.w;
            Bs[nxt][bk_ + 0][bn_] = pb.x; Bs[nxt][bk_ + 1][bn_] = pb.y;
            Bs[nxt][bk_ + 2][bn_] = pb.z; Bs[nxt][bk_ + 3][bn_] = pb.w;
            __syncthreads();
        }
    }
    float acc[8][4];
    #pragma unroll
    for (int p = 0; p < 4; p++)
        #pragma unroll
        for (int j = 0; j < 4; j++)
            unpack2(acc2[p][j], acc[2 * p][j], acc[2 * p + 1][j]);

    int col = blockIdx.x * 64 + tx * 4;
    float4 bb = *(const float4*)(bih + col);
    float bias4[4] = {bb.x, bb.y, bb.z, bb.w};
    int t  = blockIdx.y * 4 + (ty >> 2);
    int b0 = (ty & 3) * 8;
    #pragma unroll
    for (int j = 0; j < 4; j++) {
        size_t base = ((size_t)t * H3 + col + j) * BATCH + b0;
        float4 lo = make_float4(acc[0][j] + bias4[j], acc[1][j] + bias4[j],
                                acc[2][j] + bias4[j], acc[3][j] + bias4[j]);
        float4 hi = make_float4(acc[4][j] + bias4[j], acc[5][j] + bias4[j],
                                acc[6][j] + bias4[j], acc[7][j] + bias4[j]);
        *(float4*)&d_xp[base]     = lo;
        *(float4*)&d_xp[base + 4] = hi;
    }
}

// ---------------- K6: persistent GRU scan (k-split, FFMA2, 2 warps/SMSP) ----
// 128 blocks x 256 threads; block bk owns hidden units m0=bk*5..+4.
// Wsm2[k][16]: rows l=gate*5+j (15 real + 1 pad), row-pairs adjacent.
// Warp w: quarter q=w&3 covers k in [q*160,(q+1)*160); half hf=w>>2 covers
// row-pairs {hf*2, hf*2+1} of the 4 ulonglong2 (rows hf*8..hf*8+7; row 15 pad).
// 2 warps per SMSP -> FFMA2 of one warp hides the other's L2 h-load latency.
__global__ __launch_bounds__(256, 1) void k_gru(const float* __restrict__ Whh,
                                                const float* __restrict__ bhh) {
    __shared__ __align__(16) float Wsm2[HID][16];   // 40960 B
    __shared__ float part[4][15][32];               //  7680 B
    __shared__ float bhs[15];

    int bk = blockIdx.x, tid = threadIdx.x;
    int m0 = bk * 5;

    for (int idx = tid; idx < 16 * HID; idx += 256) {
        int k = idx >> 4, l = idx & 15;
        Wsm2[k][l] = (l < 15) ? Whh[((l / 5) * HID + m0 + (l % 5)) * HID + k] : 0.0f;
    }
    if (tid < 15) bhs[tid] = bhh[(tid / 5) * HID + m0 + tid % 5];
    __syncthreads();

    int b = tid & 31, w = tid >> 5;        // 8 warps
    int q = w & 3, hf = w >> 2;            // k-quarter, row-half
    int k0w = q * 160;
    int pbase = hf * 2;                    // ulonglong2 index: half0 -> [0],[1]; half1 -> [2],[3]
    int r0 = hf * 8;                       // first row of this half

    // gate item: tid < 160 handles (j = tid>>5, bb = tid&31)
    bool hasG = (tid < 160);
    int jA = tid >> 5, bbA = tid & 31;
    int mA = m0 + (hasG ? jA : 0);

    unsigned tgt = 0u;
    for (int t = 0; t < TLEN; t++) {
        const float* hb = d_hs + (size_t)t * HB + b;
        ull_t a0 = pack2(0.f, 0.f), a1 = a0, a2 = a0, a3 = a0;

        #pragma unroll 8
        for (int kk = 0; kk < 160; kk += 2) {
            int k = k0w + kk;
            float h0 = hb[(k + 0) * 32];
            float h1 = hb[(k + 1) * 32];
            ull_t hh0 = pack2(h0, h0);
            ull_t hh1 = pack2(h1, h1);
            const ulonglong2* wp0 = (const ulonglong2*)&Wsm2[k][0];
            ulonglong2 q0 = wp0[pbase], q1 = wp0[pbase + 1];
            a0 = fma2(q0.x, hh0, a0);
            a1 = fma2(q0.y, hh0, a1);
            a2 = fma2(q1.x, hh0, a2);
            a3 = fma2(q1.y, hh0, a3);
            const ulonglong2* wp1 = (const ulonglong2*)&Wsm2[k + 1][0];
            ulonglong2 s0 = wp1[pbase], s1 = wp1[pbase + 1];
            a0 = fma2(s0.x, hh1, a0);
            a1 = fma2(s0.y, hh1, a1);
            a2 = fma2(s1.x, hh1, a2);
            a3 = fma2(s1.y, hh1, a3);
        }
        // partials: rows r0..r0+7 (row 15 = pad discarded when hf==1)
        {
            float lo, hi;
            unpack2(a0, lo, hi); part[q][r0 + 0][b] = lo; part[q][r0 + 1][b] = hi;
            unpack2(a1, lo, hi); part[q][r0 + 2][b] = lo; part[q][r0 + 3][b] = hi;
            unpack2(a2, lo, hi); part[q][r0 + 4][b] = lo; part[q][r0 + 5][b] = hi;
            unpack2(a3, lo, hi); part[q][r0 + 6][b] = lo;
            if (hf == 0) part[q][7][b] = hi;
        }

        // prefetch gate inputs (independent of part[]) to hide L2 latency
        const float* xpt = d_xp + (size_t)t * H3 * BATCH;
        const float* hsl = d_hs + (size_t)t * HB;
        float xrA = 0.f, xzA = 0.f, xnA = 0.f, hoA = 0.f;
        if (hasG) {
            xrA = xpt[(size_t)mA * BATCH + bbA];
            xzA = xpt[(size_t)(640 + mA) * BATCH + bbA];
            xnA = xpt[(size_t)(1280 + mA) * BATCH + bbA];
            hoA = hsl[mA * 32 + bbA];
        }
        __syncthreads();

        if (hasG) {
            float gr = part[0][jA][bbA] + part[1][jA][bbA] + part[2][jA][bbA] + part[3][jA][bbA];
            float gz = part[0][5 + jA][bbA] + part[1][5 + jA][bbA] + part[2][5 + jA][bbA] + part[3][5 + jA][bbA];
            float gn = part[0][10 + jA][bbA] + part[1][10 + jA][bbA] + part[2][10 + jA][bbA] + part[3][10 + jA][bbA];
            float r = sigf(xrA + gr + bhs[jA]);
            float z = sigf(xzA + gz + bhs[5 + jA]);
            float n = tanhf(xnA + r * (gn + bhs[10 + jA]));
            d_hs[(size_t)(t + 1) * HB + mA * 32 + bbA] = (1.0f - z) * n + z * hoA;
        }
        __syncthreads();

        // grid barrier (monotonic counter; ring buffer => every read is first-touch)
        if (tid == 0) {
            __threadfence();
            atomicAdd(&d_cnt, 1u);
            tgt += (unsigned)NBG;
            while (*(volatile unsigned*)&d_cnt < tgt) { __nanosleep(64); }
            __threadfence();
        }
        __syncthreads();
    }
}

// ---------------- K7: FC head ----------------------------------------------
__global__ void k_fc(const float* __restrict__ fcw, const float* __restrict__ fcb,
                     float* __restrict__ out) {
    int t = blockIdx.x;
    int b = threadIdx.x & 31, mg = threadIdx.x >> 5;
    const float* h = d_hs + (size_t)(t + 1) * HB;
    float acc = 0.0f;
    for (int m = mg * 160; m < mg * 160 + 160; m++)
        acc = fmaf(fcw[m], h[m * 32 + b], acc);
    __shared__ float red[4][32];
    red[mg][b] = acc;
    __syncthreads();
    if (mg == 0)
        out[b * TLEN + t] = red[0][b] + red[1][b] + red[2][b] + red[3][b] + fcb[0];
}

// ---------------- launch ----------------------------------------------------
extern "C" void kernel_launch(void* const* d_in, const int* in_sizes, int n_in,
                              void* d_out, int out_size) {
    const float* x      = (const float*)d_in[0];
    const float* a_vals = (const float*)d_in[1];
    const float* w_vals = (const float*)d_in[2];
    const float* dcls_w = (const float*)d_in[3];
    const float* dcls_p = (const float*)d_in[4];
    const float* dcls_b = (const float*)d_in[5];
    const float* gamma  = (const float*)d_in[6];
    const float* beta   = (const float*)d_in[7];
    const float* W_ih   = (const float*)d_in[8];
    const float* W_hh   = (const float*)d_in[9];
    const float* b_ih   = (const float*)d_in[10];
    const float* b_hh   = (const float*)d_in[11];
    const float* fc_w   = (const float*)d_in[12];
    const float* fc_b   = (const float*)d_in[13];
    float* out = (float*)d_out;

    k_init<<<(HB + 255) / 256, 256>>>();
    k_front<<<dim3(FREQ, BATCH), 256>>>(x, a_vals, w_vals);
    k_dk<<<35, 256>>>(dcls_w, dcls_p);
    k_dcls<<<dim3(5, FD, BATCH), 256>>>(dcls_b);
    k_stats<<<CCH, 256>>>(gamma, beta);
    k_relayout<<<dim3(63, BATCH), 256>>>();
    k_gemm<<<dim3(30, 250), 256>>>(W_ih, b_ih);
    k_gru<<<NBG, 256>>>(W_hh, b_hh);
    k_fc<<<TLEN, 128>>>(fc_w, fc_b, out);
}